// round 4
// baseline (speedup 1.0000x reference)
#include <cuda_runtime.h>
#include <math.h>

// SLAYFeatures: out[b, r, h, p, m] = poly[b,h,p] * prf[b,r,h,m]
//   poly[b,h,p] = (xn[b,h,:] . anchors[p,:])^2 / sqrt(P)
//   prf[b,r,h,m] = sqrt(w_r/C)/sqrt(M) * exp(clip(proj*sqrt(2 s_r) - s_r, +-20))
//   proj = xn[b,h,:] . omega[r,h,:,m]
// B=8192, H=16, D=64, M=32, P=16, R=2.  Output [8192,16384] f32 (512 MB).
//
// R4: block = (32 b-rows, 1 head). omega slice + anchors + xn staged in smem,
// all compute from LDS, epilogue = pure coalesced streaming stores.

#define NB 32
#define THREADS 256
#define XPAD 68   // 64 + 4 pad floats: avoids bank conflicts on column reads

__global__ __launch_bounds__(THREADS) void slay_kernel(
    const float* __restrict__ x,        // [8192,1024]
    const float* __restrict__ omega,    // [2,16,64,32]
    const float* __restrict__ anchors,  // [16,64]
    float* __restrict__ out,            // [8192,16384]
    float s0, float s1,                 // quad nodes / C
    float c0, float c1,                 // sqrt(2*s_r)
    float e0, float e1)                 // sqrt(w_r/C)/sqrt(M)
{
    __shared__ __align__(16) float xs[NB][XPAD];        // normalized x slice (8.5 KB)
    __shared__ __align__(16) float om_s[2 * 64 * 32];   // omega[.,h,:,:]     (16 KB)
    __shared__ __align__(16) float an_s[16 * 64];       // anchors            (4 KB)
    __shared__ __align__(16) float poly_s[NB][16];      //                    (2 KB)
    __shared__ __align__(16) float prf_s[NB][2][32];    //                    (8 KB)

    const int t  = threadIdx.x;
    const int h  = blockIdx.y;
    const int b0 = blockIdx.x * NB;

    // ---------- Phase 1: stage everything ----------
    // omega slice for this head: 1024 float4, linear copy (local [r][d][m] order)
    {
        const float4* og4 = (const float4*)omega;
        float4* os4 = (float4*)om_s;
#pragma unroll
        for (int i = 0; i < 4; i++) {
            int f = i * 256 + t;                 // 0..1023
            int r = f >> 9;
            int rem = f & 511;                   // d*8 + m4
            os4[f] = og4[(size_t)(r * 16 + h) * 512 + rem];
        }
        // anchors: 256 float4 linear
        ((float4*)an_s)[t] = ((const float4*)anchors)[t];
    }
    // x slice: rows bl and bl+16, 16 float4 each; normalize via 16-lane shfl
    {
        const int bl = t >> 4;      // 0..15
        const int c  = t & 15;      // float4 column within 64-float row
        const float4* x4 = (const float4*)x;

        float4 v0 = x4[(size_t)(b0 + bl) * 256 + h * 16 + c];
        float4 v1 = x4[(size_t)(b0 + bl + 16) * 256 + h * 16 + c];
        float ss0 = v0.x*v0.x + v0.y*v0.y + v0.z*v0.z + v0.w*v0.w;
        float ss1 = v1.x*v1.x + v1.y*v1.y + v1.z*v1.z + v1.w*v1.w;
#pragma unroll
        for (int off = 8; off; off >>= 1) {
            ss0 += __shfl_xor_sync(0xffffffffu, ss0, off);
            ss1 += __shfl_xor_sync(0xffffffffu, ss1, off);
        }
        float inv0 = 1.0f / (sqrtf(fmaxf(ss0, 1e-12f)) + 1e-4f);
        float inv1 = 1.0f / (sqrtf(fmaxf(ss1, 1e-12f)) + 1e-4f);
        v0.x *= inv0; v0.y *= inv0; v0.z *= inv0; v0.w *= inv0;
        v1.x *= inv1; v1.y *= inv1; v1.z *= inv1; v1.w *= inv1;
        *(float4*)&xs[bl][c * 4]      = v0;
        *(float4*)&xs[bl + 16][c * 4] = v1;
    }
    __syncthreads();

    // ---------- Phase 2: poly. thread = (bl in {q, q+16}, p) ----------
    {
        const int q = t >> 4;        // 0..15
        const int p = t & 15;
        float a0 = 0.f, a1 = 0.f;
        const float4* an = (const float4*)(an_s + p * 64);
#pragma unroll 4
        for (int d4 = 0; d4 < 16; d4++) {
            float4 a = an[d4];
            float4 u = *(const float4*)&xs[q][d4 * 4];
            float4 w = *(const float4*)&xs[q + 16][d4 * 4];
            a0 += u.x*a.x + u.y*a.y + u.z*a.z + u.w*a.w;
            a1 += w.x*a.x + w.y*a.y + w.z*a.z + w.w*a.w;
        }
        poly_s[q][p]      = a0 * a0 * 0.25f;   // /sqrt(P=16)
        poly_s[q + 16][p] = a1 * a1 * 0.25f;
    }

    // ---------- Phase 3a: PRF from smem. thread = (bl, r, m8) ----------
    {
        const int bl = t >> 3;          // 0..31
        const int r  = (t >> 2) & 1;
        const int m8 = t & 3;           // 8 m-values: m8*8 .. m8*8+7

        float4 a0 = make_float4(0.f, 0.f, 0.f, 0.f);
        float4 a1 = make_float4(0.f, 0.f, 0.f, 0.f);
        const float4* om4 = (const float4*)om_s + (size_t)r * 128 * 4 + m8 * 2;
        const float* xr = xs[bl];
#pragma unroll 8
        for (int d = 0; d < 64; d++) {
            float xv = xr[d];
            float4 o0 = om4[d * 8];
            float4 o1 = om4[d * 8 + 1];
            a0.x += xv * o0.x; a0.y += xv * o0.y; a0.z += xv * o0.z; a0.w += xv * o0.w;
            a1.x += xv * o1.x; a1.y += xv * o1.y; a1.z += xv * o1.z; a1.w += xv * o1.w;
        }
        const float sr = r ? s1 : s0;
        const float cr = r ? c1 : c0;
        const float er = r ? e1 : e0;
        float4 p0, p1;
        p0.x = er * __expf(fminf(fmaxf(a0.x * cr - sr, -20.f), 20.f));
        p0.y = er * __expf(fminf(fmaxf(a0.y * cr - sr, -20.f), 20.f));
        p0.z = er * __expf(fminf(fmaxf(a0.z * cr - sr, -20.f), 20.f));
        p0.w = er * __expf(fminf(fmaxf(a0.w * cr - sr, -20.f), 20.f));
        p1.x = er * __expf(fminf(fmaxf(a1.x * cr - sr, -20.f), 20.f));
        p1.y = er * __expf(fminf(fmaxf(a1.y * cr - sr, -20.f), 20.f));
        p1.z = er * __expf(fminf(fmaxf(a1.z * cr - sr, -20.f), 20.f));
        p1.w = er * __expf(fminf(fmaxf(a1.w * cr - sr, -20.f), 20.f));
        *(float4*)&prf_s[bl][r][m8 * 8]     = p0;
        *(float4*)&prf_s[bl][r][m8 * 8 + 4] = p1;
    }
    __syncthreads();

    // ---------- Phase 3b: outer product, coalesced streaming stores ----------
    // 64 (bl, r) pairs; warp w handles pairs w, w+8, ..., w+56.
    // Per pair: 128 contiguous float4 written in 4 iters of 32 lanes (512 B/iter).
    {
        const int w    = t >> 5;
        const int lane = t & 31;
        const int pq   = lane >> 3;     // p sub-index within iter
        const int m4   = lane & 7;

#pragma unroll
        for (int i = 0; i < 8; i++) {
            const int q  = w + i * 8;   // pair id
            const int bl = q >> 1;
            const int r  = q & 1;
            float4 pr = ((const float4*)prf_s[bl][r])[m4];
            float* ob = out + (size_t)(b0 + bl) * 16384 + r * 8192 + h * 512 + m4 * 4;
#pragma unroll
            for (int it = 0; it < 4; it++) {
                const int p = it * 4 + pq;
                float pf = poly_s[bl][p];
                float4 o;
                o.x = pf * pr.x; o.y = pf * pr.y; o.z = pf * pr.z; o.w = pf * pr.w;
                __stcs((float4*)(ob + p * 32), o);
            }
        }
    }
}

extern "C" void kernel_launch(void* const* d_in, const int* in_sizes, int n_in,
                              void* d_out, int out_size) {
    const float* x       = (const float*)d_in[0];
    const float* omega   = (const float*)d_in[1];
    const float* anchors = (const float*)d_in[2];
    float* out = (float*)d_out;

    // Gauss-Laguerre (n=2) nodes/weights, scaled by 1/C, in double then f32.
    const double C   = 2.0 + 1e-6;
    const double rt2 = 1.4142135623730951;
    const double n0d = 2.0 - rt2, n1d = 2.0 + rt2;
    const double w0d = (2.0 + rt2) / 4.0, w1d = (2.0 - rt2) / 4.0;

    float s0 = (float)(n0d / C);
    float s1 = (float)(n1d / C);
    float c0 = sqrtf(2.0f * s0);
    float c1 = sqrtf(2.0f * s1);
    float invSqrtM = 1.0f / sqrtf(32.0f);
    float e0 = sqrtf((float)(w0d / C)) * invSqrtM;
    float e1 = sqrtf((float)(w1d / C)) * invSqrtM;

    dim3 grid(8192 / NB, 16);
    dim3 block(THREADS);
    slay_kernel<<<grid, block>>>(x, omega, anchors, out, s0, s1, c0, c1, e0, e1);
    (void)in_sizes; (void)n_in; (void)out_size;
}

// round 6
// speedup vs baseline: 1.9672x; 1.9672x over previous
#include <cuda_runtime.h>
#include <math.h>

// SLAYFeatures: out[b, r, h, p, m] = poly[b,h,p] * prf[b,r,h,m]
//   poly[b,h,p] = (xn[b,h,:] . anchors[p,:])^2 / sqrt(P)
//   prf[b,r,h,m] = sqrt(w_r/C)/sqrt(M) * exp(clip(proj*sqrt(2 s_r) - s_r, +-20))
//   proj = xn[b,h,:] . omega[r,h,:,m]
// B=8192, H=16, D=64, M=32, P=16, R=2.  Output [8192,16384] f32 (512 MB) -> store-bound.
//
// R5 = R2 structure (best: omega via LDG/L2, register accumulators) +
//   __launch_bounds__(256,3) for 24 warps/SM, __expf, streaming stores.

#define NB 8          // b-rows per block (amortizes omega L2 traffic 8x)
#define THREADS 256

__global__ __launch_bounds__(THREADS, 3) void slay_kernel(
    const float* __restrict__ x,        // [8192,1024]
    const float* __restrict__ omega,    // [2,16,64,32]
    const float* __restrict__ anchors,  // [16,64]
    float* __restrict__ out,            // [8192,16384]
    float s0, float s1,                 // quad nodes / C
    float c0, float c1,                 // sqrt(2*s_r)
    float e0, float e1)                 // sqrt(w_r/C)/sqrt(M)
{
    __shared__ __align__(16) float xs[NB][1024];   // normalized x rows (32 KB)
    __shared__ __align__(16) float poly[NB][256];  // [b][h*16+p]        (8 KB)

    const int t  = threadIdx.x;
    const int b0 = blockIdx.x * NB;

    // ---------- Phase 1: load x, per-head normalize ----------
    // float4 #t of each row covers floats [4t,4t+4) -> head = t/16; the 16
    // threads sharing a head are 16 consecutive lanes -> shfl_xor reduce.
    {
        float4 v[NB];
        float  ss[NB];
        const float4* x4 = (const float4*)x;
#pragma unroll
        for (int k = 0; k < NB; k++) {
            v[k] = x4[(size_t)(b0 + k) * 256 + t];
            ss[k] = v[k].x*v[k].x + v[k].y*v[k].y + v[k].z*v[k].z + v[k].w*v[k].w;
        }
#pragma unroll
        for (int k = 0; k < NB; k++) {
#pragma unroll
            for (int off = 8; off; off >>= 1)
                ss[k] += __shfl_xor_sync(0xffffffffu, ss[k], off);
            float inv = 1.0f / (sqrtf(fmaxf(ss[k], 1e-12f)) + 1e-4f);
            float4 w = v[k];
            w.x *= inv; w.y *= inv; w.z *= inv; w.w *= inv;
            ((float4*)xs[k])[t] = w;
        }
    }
    __syncthreads();

    // ---------- Phase 2: poly features. thread = (h, p) ----------
    {
        const int h = t >> 4, p = t & 15;
        float acc[NB];
#pragma unroll
        for (int k = 0; k < NB; k++) acc[k] = 0.0f;
        const float4* an = (const float4*)(anchors + p * 64);
#pragma unroll 4
        for (int d4 = 0; d4 < 16; d4++) {
            float4 a = an[d4];
#pragma unroll
            for (int k = 0; k < NB; k++) {
                float4 xv = ((const float4*)xs[k])[h * 16 + d4];
                acc[k] += xv.x*a.x + xv.y*a.y + xv.z*a.z + xv.w*a.w;
            }
        }
#pragma unroll
        for (int k = 0; k < NB; k++)
            poly[k][t] = acc[k] * acc[k] * 0.25f;   // /sqrt(P=16)
    }
    __syncthreads();

    // ---------- Phase 3: PRF features + fused outer-product store ----------
    // thread = (r, h, m4): 4 consecutive m per thread (float4 omega loads,
    // m-contiguous -> coalesced), 8 b-rows in registers.
    {
        const int r  = t >> 7;
        const int h  = (t >> 3) & 15;
        const int m4 = t & 7;

        float4 acc[NB];
#pragma unroll
        for (int k = 0; k < NB; k++) acc[k] = make_float4(0.f, 0.f, 0.f, 0.f);

        const float4* og = (const float4*)omega + (size_t)((r * 16 + h) * 64) * 8 + m4;
#pragma unroll 4
        for (int d4 = 0; d4 < 16; d4++) {
            float4 o0 = og[(4 * d4 + 0) * 8];
            float4 o1 = og[(4 * d4 + 1) * 8];
            float4 o2 = og[(4 * d4 + 2) * 8];
            float4 o3 = og[(4 * d4 + 3) * 8];
#pragma unroll
            for (int k = 0; k < NB; k++) {
                float4 xv = ((const float4*)xs[k])[h * 16 + d4];
                acc[k].x += xv.x*o0.x; acc[k].y += xv.x*o0.y; acc[k].z += xv.x*o0.z; acc[k].w += xv.x*o0.w;
                acc[k].x += xv.y*o1.x; acc[k].y += xv.y*o1.y; acc[k].z += xv.y*o1.z; acc[k].w += xv.y*o1.w;
                acc[k].x += xv.z*o2.x; acc[k].y += xv.z*o2.y; acc[k].z += xv.z*o2.z; acc[k].w += xv.z*o2.w;
                acc[k].x += xv.w*o3.x; acc[k].y += xv.w*o3.y; acc[k].z += xv.w*o3.z; acc[k].w += xv.w*o3.w;
            }
        }

        const float sr = r ? s1 : s0;
        const float cr = r ? c1 : c0;
        const float er = r ? e1 : e0;

#pragma unroll
        for (int k = 0; k < NB; k++) {
            float4 a = acc[k];
            float4 pr;
            pr.x = er * __expf(fminf(fmaxf(a.x * cr - sr, -20.f), 20.f));
            pr.y = er * __expf(fminf(fmaxf(a.y * cr - sr, -20.f), 20.f));
            pr.z = er * __expf(fminf(fmaxf(a.z * cr - sr, -20.f), 20.f));
            pr.w = er * __expf(fminf(fmaxf(a.w * cr - sr, -20.f), 20.f));

            float* ob = out + (size_t)(b0 + k) * 16384 + r * 8192 + h * 512 + m4 * 4;
            const float* pl = &poly[k][h * 16];
#pragma unroll
            for (int p = 0; p < 16; p++) {
                float pf = pl[p];
                float4 o;
                o.x = pf * pr.x; o.y = pf * pr.y; o.z = pf * pr.z; o.w = pf * pr.w;
                __stcs((float4*)(ob + p * 32), o);   // streaming store: write-once output
            }
        }
    }
}

extern "C" void kernel_launch(void* const* d_in, const int* in_sizes, int n_in,
                              void* d_out, int out_size) {
    const float* x       = (const float*)d_in[0];
    const float* omega   = (const float*)d_in[1];
    const float* anchors = (const float*)d_in[2];
    float* out = (float*)d_out;

    // Gauss-Laguerre (n=2) nodes/weights, scaled by 1/C, in double then f32.
    const double C   = 2.0 + 1e-6;
    const double rt2 = 1.4142135623730951;
    const double n0d = 2.0 - rt2, n1d = 2.0 + rt2;
    const double w0d = (2.0 + rt2) / 4.0, w1d = (2.0 - rt2) / 4.0;

    float s0 = (float)(n0d / C);
    float s1 = (float)(n1d / C);
    float c0 = sqrtf(2.0f * s0);
    float c1 = sqrtf(2.0f * s1);
    float invSqrtM = 1.0f / sqrtf(32.0f);
    float e0 = sqrtf((float)(w0d / C)) * invSqrtM;
    float e1 = sqrtf((float)(w1d / C)) * invSqrtM;

    dim3 grid(8192 / NB);
    dim3 block(THREADS);
    slay_kernel<<<grid, block>>>(x, omega, anchors, out, s0, s1, c0, c1, e0, e1);
    (void)in_sizes; (void)n_in; (void)out_size;
}